// round 1
// baseline (speedup 1.0000x reference)
#include <cuda_runtime.h>

#define BLOCK 128

typedef unsigned long long u64;

// ---------------- f32x2 helpers (sm_100+) ----------------
__device__ __forceinline__ u64 pack2(float x) {
    u64 r;
    asm("mov.b64 %0, {%1, %1};" : "=l"(r) : "f"(x));
    return r;
}
__device__ __forceinline__ void fma2(u64& d, u64 a, u64 b) {
    asm("fma.rn.f32x2 %0, %1, %2, %3;" : "=l"(d) : "l"(a), "l"(b), "l"(d));
}
__device__ __forceinline__ void unpack2(u64 v, float& lo, float& hi) {
    asm("mov.b64 {%0, %1}, %2;" : "=f"(lo), "=f"(hi) : "l"(v));
}

// exact branchless elu: x>0 -> x ; x<=0 -> exp(x)-1
__device__ __forceinline__ float elu_f(float x) {
    return fmaxf(x, 0.f) + __expf(fminf(x, 0.f)) - 1.f;
}

// ---------------- scratch (no allocations allowed) ----------------
__device__ float g_buf0[524288];
__device__ float g_buf1[65536];
__device__ float g_buf2[8192];

// shared layout size in floats
__host__ __device__ constexpr int smem_floats(int CIN) {
    return 160 * BLOCK                  // hs: [160][BLOCK]
         + 2 * (CIN + 10) * 10 * 4      // packed W|U float4 per dir/k/j
         + 2 * 10 * 4                   // packed bias
         + 2 * 20 * 4                   // LSTM2 V
         + 8 + 8                        // LSTM2 R, C (2 x float4 each)
         + BLOCK * (8 * CIN + 3);       // padded per-thread x
}

// One "aggregator" level: in[nseq*8*CIN] -> out[nseq]
// LSTM1: H=10, act=elu, rec_act=elu, bidirectional, return_sequences
// LSTM2: H=1,  act=ident, rec_act=elu, bidirectional, last state
// out = sigmoid(mean(h2f, h2b))
template <int CIN>
__global__ void __launch_bounds__(BLOCK, 2)
agg_kernel(const float* __restrict__ in, float* __restrict__ out,
           const float* __restrict__ wf, const float* __restrict__ uf, const float* __restrict__ bf,
           const float* __restrict__ wb, const float* __restrict__ ub, const float* __restrict__ bb,
           const float* __restrict__ v2f, const float* __restrict__ r2f, const float* __restrict__ c2f,
           const float* __restrict__ v2b, const float* __restrict__ r2b, const float* __restrict__ c2b,
           int nseq)
{
    extern __shared__ float smem[];
    constexpr int KTOT = CIN + 10;
    constexpr int XW = 8 * CIN + 3;     // odd padding -> conflict-free scalar reads

    float*  hsm = smem;                                  // [160][BLOCK]
    float4* sWU = (float4*)(smem + 160 * BLOCK);         // [2][KTOT][10]
    float4* sB  = sWU + 2 * KTOT * 10;                   // [2][10]
    float4* sV  = sB + 20;                               // [2][20]
    float4* sR  = sV + 40;                               // [2]
    float4* sC  = sR + 2;                                // [2]
    float*  xs  = (float*)(sC + 2);                      // [BLOCK][XW]

    const int tid = threadIdx.x;

    // ---- stage LSTM1 weights, permuted to (unit-pair, gate) float4 layout ----
    // j in 0..9: mp=j>>1 (unit pair), gp=j&1 (gate pair)
    // float4 = { W[k][2gp*10+2mp], W[k][2gp*10+2mp+1], W[k][(2gp+1)*10+2mp], W[k][(2gp+1)*10+2mp+1] }
    for (int i = tid; i < 2 * KTOT * 10; i += BLOCK) {
        int d = i / (KTOT * 10);
        int r = i - d * (KTOT * 10);
        int k = r / 10;
        int j = r - k * 10;
        const float* W = (k < CIN) ? (((d == 0) ? wf : wb) + k * 40)
                                   : (((d == 0) ? uf : ub) + (k - CIN) * 40);
        int mp = j >> 1, gp = j & 1;
        int c0 = (2 * gp) * 10 + 2 * mp;
        int c2 = (2 * gp + 1) * 10 + 2 * mp;
        sWU[i] = make_float4(W[c0], W[c0 + 1], W[c2], W[c2 + 1]);
    }
    for (int i = tid; i < 20; i += BLOCK) {
        int d = i / 10, j = i % 10;
        const float* B = (d == 0) ? bf : bb;
        int mp = j >> 1, gp = j & 1;
        int c0 = (2 * gp) * 10 + 2 * mp;
        int c2 = (2 * gp + 1) * 10 + 2 * mp;
        sB[i] = make_float4(B[c0], B[c0 + 1], B[c2], B[c2 + 1]);
    }
    for (int i = tid; i < 40; i += BLOCK) {
        int d = i / 20, k = i % 20;
        const float* V = (d == 0) ? v2f : v2b;
        sV[i] = make_float4(V[k * 4 + 0], V[k * 4 + 1], V[k * 4 + 2], V[k * 4 + 3]);
    }
    if (tid < 2) {
        const float* R = (tid == 0) ? r2f : r2b;
        const float* C = (tid == 0) ? c2f : c2b;
        sR[tid] = make_float4(R[0], R[1], R[2], R[3]);
        sC[tid] = make_float4(C[0], C[1], C[2], C[3]);
    }

    // ---- stage x (coalesced global -> padded per-thread rows in shared) ----
    {
        long long base  = (long long)blockIdx.x * BLOCK * (8 * CIN);
        long long limit = (long long)nseq * 8 * CIN;
        const int total = BLOCK * 8 * CIN;
        for (int i = tid; i < total; i += BLOCK) {
            float v = (base + i < limit) ? in[base + i] : 0.f;
            xs[(i / (8 * CIN)) * XW + (i % (8 * CIN))] = v;
        }
    }
    __syncthreads();

    const int n = blockIdx.x * BLOCK + tid;
    if (n >= nseq) return;

    const float* myx = xs + tid * XW;

    // ================= LSTM1, both directions =================
    for (int d = 0; d < 2; d++) {
        float h[10], c[10];
#pragma unroll
        for (int m = 0; m < 10; m++) { h[m] = 0.f; c[m] = 0.f; }
        const float4* WU = sWU + d * KTOT * 10;
        const float4* Bv = sB + d * 10;

        for (int s = 0; s < 8; s++) {
            const int t = d ? (7 - s) : s;   // backward scan stores at position t
            u64 acc[20];                      // acc[mp*4+g] = z pair (units 2mp,2mp+1) of gate g
#pragma unroll
            for (int j = 0; j < 10; j++) {
                ulonglong2 bq = *(const ulonglong2*)&Bv[j];
                int p = (j >> 1) * 4 + 2 * (j & 1);
                acc[p] = bq.x; acc[p + 1] = bq.y;
            }
#pragma unroll
            for (int k = 0; k < CIN; k++) {
                u64 a = pack2(myx[t * CIN + k]);
#pragma unroll
                for (int j = 0; j < 10; j++) {
                    ulonglong2 wq = *(const ulonglong2*)&WU[k * 10 + j];
                    int p = (j >> 1) * 4 + 2 * (j & 1);
                    fma2(acc[p], a, wq.x);
                    fma2(acc[p + 1], a, wq.y);
                }
            }
#pragma unroll
            for (int k = 0; k < 10; k++) {
                u64 a = pack2(h[k]);
#pragma unroll
                for (int j = 0; j < 10; j++) {
                    ulonglong2 wq = *(const ulonglong2*)&WU[(CIN + k) * 10 + j];
                    int p = (j >> 1) * 4 + 2 * (j & 1);
                    fma2(acc[p], a, wq.x);
                    fma2(acc[p + 1], a, wq.y);
                }
            }
            // gates: order i, f, g, o ; c = elu(f)*c + elu(i)*elu(g) ; h = elu(o)*elu(c)
#pragma unroll
            for (int mp = 0; mp < 5; mp++) {
                float i0, i1, f0, f1, g0, g1, o0, o1;
                unpack2(acc[mp * 4 + 0], i0, i1);
                unpack2(acc[mp * 4 + 1], f0, f1);
                unpack2(acc[mp * 4 + 2], g0, g1);
                unpack2(acc[mp * 4 + 3], o0, o1);
                const int m0 = 2 * mp;
                c[m0]     = elu_f(f0) * c[m0]     + elu_f(i0) * elu_f(g0);
                c[m0 + 1] = elu_f(f1) * c[m0 + 1] + elu_f(i1) * elu_f(g1);
                float hh0 = elu_f(o0) * elu_f(c[m0]);
                float hh1 = elu_f(o1) * elu_f(c[m0 + 1]);
                h[m0] = hh0; h[m0 + 1] = hh1;
                hsm[(d * 80 + t * 10 + m0) * BLOCK + tid]     = hh0;
                hsm[(d * 80 + t * 10 + m0 + 1) * BLOCK + tid] = hh1;
            }
        }
    }

    // ================= LSTM2 (H=1), both directions =================
    float res[2];
    for (int d2 = 0; d2 < 2; d2++) {
        ulonglong2 rq = *(const ulonglong2*)&sR[d2];
        ulonglong2 cq = *(const ulonglong2*)&sC[d2];
        const float4* V = sV + d2 * 20;
        float h2 = 0.f, c2v = 0.f;
        for (int s = 0; s < 8; s++) {
            const int t = d2 ? (7 - s) : s;
            u64 z01 = cq.x, z23 = cq.y;   // bias init
#pragma unroll
            for (int k = 0; k < 20; k++) {
                const int slot = (k < 10) ? (t * 10 + k) : (80 + t * 10 + (k - 10));
                u64 a = pack2(hsm[slot * BLOCK + tid]);
                ulonglong2 vq = *(const ulonglong2*)&V[k];
                fma2(z01, a, vq.x);
                fma2(z23, a, vq.y);
            }
            {
                u64 a = pack2(h2);
                fma2(z01, a, rq.x);
                fma2(z23, a, rq.y);
            }
            float z0, z1, z2, z3;
            unpack2(z01, z0, z1);
            unpack2(z23, z2, z3);
            // i=elu(z0), f=elu(z1), g=z2 (identity), o=elu(z3); act=ident -> h = elu(o)*c
            c2v = elu_f(z1) * c2v + elu_f(z0) * z2;
            h2  = elu_f(z3) * c2v;
        }
        res[d2] = h2;
    }
    const float m = 0.5f * (res[0] + res[1]);
    out[n] = 1.f / (1.f + __expf(-m));
}

extern "C" void kernel_launch(void* const* d_in, const int* in_sizes, int n_in,
                              void* d_out, int out_size)
{
    const float* x   = (const float*)d_in[0];
    const float* w0f = (const float*)d_in[1];
    const float* u0f = (const float*)d_in[2];
    const float* b0f = (const float*)d_in[3];
    const float* w0b = (const float*)d_in[4];
    const float* u0b = (const float*)d_in[5];
    const float* b0b = (const float*)d_in[6];
    const float* w1f = (const float*)d_in[7];   // [3,1,40]
    const float* u1f = (const float*)d_in[8];   // [3,10,40]
    const float* b1f = (const float*)d_in[9];   // [3,40]
    const float* w1b = (const float*)d_in[10];
    const float* u1b = (const float*)d_in[11];
    const float* b1b = (const float*)d_in[12];
    const float* vF  = (const float*)d_in[13];  // [4,20,4]
    const float* rF  = (const float*)d_in[14];  // [4,1,4]
    const float* cF  = (const float*)d_in[15];  // [4,4]
    const float* vB  = (const float*)d_in[16];
    const float* rB  = (const float*)d_in[17];
    const float* cB  = (const float*)d_in[18];
    float* out = (float*)d_out;

    float *buf0, *buf1, *buf2;
    cudaGetSymbolAddress((void**)&buf0, g_buf0);
    cudaGetSymbolAddress((void**)&buf1, g_buf1);
    cudaGetSymbolAddress((void**)&buf2, g_buf2);

    const size_t smem5 = (size_t)smem_floats(5) * sizeof(float);
    const size_t smem1 = (size_t)smem_floats(1) * sizeof(float);
    cudaFuncSetAttribute(agg_kernel<5>, cudaFuncAttributeMaxDynamicSharedMemorySize, (int)smem5);
    cudaFuncSetAttribute(agg_kernel<1>, cudaFuncAttributeMaxDynamicSharedMemorySize, (int)smem1);

    // level 0: x[16,262144,5] -> buf0[524288]
    agg_kernel<5><<<524288 / BLOCK, BLOCK, smem5>>>(
        x, buf0,
        w0f, u0f, b0f, w0b, u0b, b0b,
        vF + 0, rF + 0, cF + 0, vB + 0, rB + 0, cB + 0,
        524288);

    // level 1: buf0 -> buf1[65536]
    agg_kernel<1><<<65536 / BLOCK, BLOCK, smem1>>>(
        buf0, buf1,
        w1f + 0 * 40, u1f + 0 * 400, b1f + 0 * 40,
        w1b + 0 * 40, u1b + 0 * 400, b1b + 0 * 40,
        vF + 1 * 80, rF + 1 * 4, cF + 1 * 4,
        vB + 1 * 80, rB + 1 * 4, cB + 1 * 4,
        65536);

    // level 2: buf1 -> buf2[8192]
    agg_kernel<1><<<8192 / BLOCK, BLOCK, smem1>>>(
        buf1, buf2,
        w1f + 1 * 40, u1f + 1 * 400, b1f + 1 * 40,
        w1b + 1 * 40, u1b + 1 * 400, b1b + 1 * 40,
        vF + 2 * 80, rF + 2 * 4, cF + 2 * 4,
        vB + 2 * 80, rB + 2 * 4, cB + 2 * 4,
        8192);

    // level 3: buf2 -> out[1024]  ([16,64,1])
    agg_kernel<1><<<1024 / BLOCK, BLOCK, smem1>>>(
        buf2, out,
        w1f + 2 * 40, u1f + 2 * 400, b1f + 2 * 40,
        w1b + 2 * 40, u1b + 2 * 400, b1b + 2 * 40,
        vF + 3 * 80, rF + 3 * 4, cF + 3 * 4,
        vB + 3 * 80, rB + 3 * 4, cB + 3 * 4,
        1024);
}

// round 2
// speedup vs baseline: 1.0844x; 1.0844x over previous
#include <cuda_runtime.h>

#define BLOCK 64
#define S 32        // sequences per block (2 threads per sequence)
#define SP 33       // padded hsm column stride

typedef unsigned long long u64;

// ---------------- f32x2 helpers (sm_100+) ----------------
__device__ __forceinline__ u64 pack2(float x) {
    u64 r;
    asm("mov.b64 %0, {%1, %1};" : "=l"(r) : "f"(x));
    return r;
}
__device__ __forceinline__ void fma2(u64& d, u64 a, u64 b) {
    asm("fma.rn.f32x2 %0, %1, %2, %3;" : "=l"(d) : "l"(a), "l"(b), "l"(d));
}
__device__ __forceinline__ void unpack2(u64 v, float& lo, float& hi) {
    asm("mov.b64 {%0, %1}, %2;" : "=f"(lo), "=f"(hi) : "l"(v));
}

// exact branchless elu: x>0 -> x ; x<=0 -> exp(x)-1
__device__ __forceinline__ float elu_f(float x) {
    return fmaxf(x, 0.f) + __expf(fminf(x, 0.f)) - 1.f;
}

// ---------------- scratch (no allocations allowed) ----------------
__device__ float g_buf0[524288];
__device__ float g_buf1[65536];
__device__ float g_buf2[8192];

__host__ __device__ constexpr int smem_floats(int CIN) {
    return 160 * SP                     // hsm: [160][SP]
         + 2 * (CIN + 10) * 10 * 4      // packed W|U float4 per dir/k/j
         + 2 * 10 * 4                   // packed bias
         + 2 * 20 * 4                   // LSTM2 V
         + 8 + 8                        // LSTM2 R, C
         + S * (8 * CIN + 1);           // padded per-seq x rows
}

// One "aggregator" level, direction-split: thread pair (2s, 2s+1) handles
// sequence s; even thread = forward LSTM, odd = backward.
template <int CIN>
__global__ void __launch_bounds__(BLOCK, 7)
agg_kernel(const float* __restrict__ in, float* __restrict__ out,
           const float* __restrict__ wf, const float* __restrict__ uf, const float* __restrict__ bf,
           const float* __restrict__ wb, const float* __restrict__ ub, const float* __restrict__ bb,
           const float* __restrict__ v2f, const float* __restrict__ r2f, const float* __restrict__ c2f,
           const float* __restrict__ v2b, const float* __restrict__ r2b, const float* __restrict__ c2b)
{
    extern __shared__ float smem[];
    constexpr int KTOT = CIN + 10;
    constexpr int XW = 8 * CIN + 1;     // odd stride -> conflict-free

    float*  hsm = smem;                                  // [160][SP]
    float4* sWU = (float4*)(smem + 160 * SP);            // [2][KTOT][10]
    float4* sB  = sWU + 2 * KTOT * 10;                   // [2][10]
    float4* sV  = sB + 20;                               // [2][20]
    float4* sR  = sV + 40;                               // [2]
    float4* sC  = sR + 2;                                // [2]
    float*  xs  = (float*)(sC + 2);                      // [S][XW]

    const int tid = threadIdx.x;

    // ---- stage LSTM1 weights, permuted to (unit-pair, gate) float4 layout ----
    for (int i = tid; i < 2 * KTOT * 10; i += BLOCK) {
        int d = i / (KTOT * 10);
        int r = i - d * (KTOT * 10);
        int k = r / 10;
        int j = r - k * 10;
        const float* W = (k < CIN) ? (((d == 0) ? wf : wb) + k * 40)
                                   : (((d == 0) ? uf : ub) + (k - CIN) * 40);
        int mp = j >> 1, gp = j & 1;
        int c0 = (2 * gp) * 10 + 2 * mp;
        int c2 = (2 * gp + 1) * 10 + 2 * mp;
        sWU[i] = make_float4(W[c0], W[c0 + 1], W[c2], W[c2 + 1]);
    }
    for (int i = tid; i < 20; i += BLOCK) {
        int d = i / 10, j = i % 10;
        const float* B = (d == 0) ? bf : bb;
        int mp = j >> 1, gp = j & 1;
        int c0 = (2 * gp) * 10 + 2 * mp;
        int c2 = (2 * gp + 1) * 10 + 2 * mp;
        sB[i] = make_float4(B[c0], B[c0 + 1], B[c2], B[c2 + 1]);
    }
    for (int i = tid; i < 40; i += BLOCK) {
        int d = i / 20, k = i % 20;
        const float* V = (d == 0) ? v2f : v2b;
        sV[i] = make_float4(V[k * 4 + 0], V[k * 4 + 1], V[k * 4 + 2], V[k * 4 + 3]);
    }
    if (tid < 2) {
        const float* R = (tid == 0) ? r2f : r2b;
        const float* C = (tid == 0) ? c2f : c2b;
        sR[tid] = make_float4(R[0], R[1], R[2], R[3]);
        sC[tid] = make_float4(C[0], C[1], C[2], C[3]);
    }

    // ---- stage x (coalesced; grid sizes divide exactly, no bounds needed) ----
    {
        long long base = (long long)blockIdx.x * S * (8 * CIN);
        const int total = S * 8 * CIN;
        for (int i = tid; i < total; i += BLOCK)
            xs[(i / (8 * CIN)) * XW + (i % (8 * CIN))] = in[base + i];
    }
    __syncthreads();

    const int seq = tid >> 1;
    const int dir = tid & 1;
    const float* myx = xs + seq * XW;
    const float4* WU = sWU + dir * KTOT * 10;
    const float4* Bv = sB + dir * 10;

    // ================= LSTM1, one direction per thread =================
    {
        float h[10], c[10];
#pragma unroll
        for (int m = 0; m < 10; m++) { h[m] = 0.f; c[m] = 0.f; }

        for (int s = 0; s < 8; s++) {
            const int t = dir ? (7 - s) : s;
            u64 acc[20];                  // acc[mp*4+g] = z pair of gate g
#pragma unroll
            for (int j = 0; j < 10; j++) {
                ulonglong2 bq = *(const ulonglong2*)&Bv[j];
                int p = (j >> 1) * 4 + 2 * (j & 1);
                acc[p] = bq.x; acc[p + 1] = bq.y;
            }
#pragma unroll
            for (int k = 0; k < CIN; k++) {
                u64 a = pack2(myx[t * CIN + k]);
#pragma unroll
                for (int j = 0; j < 10; j++) {
                    ulonglong2 wq = *(const ulonglong2*)&WU[k * 10 + j];
                    int p = (j >> 1) * 4 + 2 * (j & 1);
                    fma2(acc[p], a, wq.x);
                    fma2(acc[p + 1], a, wq.y);
                }
            }
#pragma unroll
            for (int k = 0; k < 10; k++) {
                u64 a = pack2(h[k]);
#pragma unroll
                for (int j = 0; j < 10; j++) {
                    ulonglong2 wq = *(const ulonglong2*)&WU[(CIN + k) * 10 + j];
                    int p = (j >> 1) * 4 + 2 * (j & 1);
                    fma2(acc[p], a, wq.x);
                    fma2(acc[p + 1], a, wq.y);
                }
            }
            // gates i,f,g,o: c = elu(f)*c + elu(i)*elu(g); h = elu(o)*elu(c)
#pragma unroll
            for (int mp = 0; mp < 5; mp++) {
                float i0, i1, f0, f1, g0, g1, o0, o1;
                unpack2(acc[mp * 4 + 0], i0, i1);
                unpack2(acc[mp * 4 + 1], f0, f1);
                unpack2(acc[mp * 4 + 2], g0, g1);
                unpack2(acc[mp * 4 + 3], o0, o1);
                const int m0 = 2 * mp;
                c[m0]     = elu_f(f0) * c[m0]     + elu_f(i0) * elu_f(g0);
                c[m0 + 1] = elu_f(f1) * c[m0 + 1] + elu_f(i1) * elu_f(g1);
                float hh0 = elu_f(o0) * elu_f(c[m0]);
                float hh1 = elu_f(o1) * elu_f(c[m0 + 1]);
                h[m0] = hh0; h[m0 + 1] = hh1;
                hsm[(dir * 80 + t * 10 + m0) * SP + seq]     = hh0;
                hsm[(dir * 80 + t * 10 + m0 + 1) * SP + seq] = hh1;
            }
        }
    }
    __syncthreads();

    // ================= LSTM2 (H=1), one direction per thread =================
    float h2;
    {
        const int d2 = dir;
        ulonglong2 rq = *(const ulonglong2*)&sR[d2];
        ulonglong2 cq = *(const ulonglong2*)&sC[d2];
        const float4* V = sV + d2 * 20;
        h2 = 0.f;
        float c2v = 0.f;
        for (int s = 0; s < 8; s++) {
            const int t = d2 ? (7 - s) : s;
            u64 z01 = cq.x, z23 = cq.y;   // bias init
#pragma unroll
            for (int k = 0; k < 20; k++) {
                const int slot = (k < 10) ? (t * 10 + k) : (80 + t * 10 + (k - 10));
                u64 a = pack2(hsm[slot * SP + seq]);
                ulonglong2 vq = *(const ulonglong2*)&V[k];
                fma2(z01, a, vq.x);
                fma2(z23, a, vq.y);
            }
            {
                u64 a = pack2(h2);
                fma2(z01, a, rq.x);
                fma2(z23, a, rq.y);
            }
            float z0, z1, z2, z3;
            unpack2(z01, z0, z1);
            unpack2(z23, z2, z3);
            c2v = elu_f(z1) * c2v + elu_f(z0) * z2;   // g is identity
            h2  = elu_f(z3) * c2v;
        }
    }

    // combine fwd/bwd across the thread pair
    float other = __shfl_xor_sync(0xFFFFFFFFu, h2, 1);
    if (dir == 0) {
        float m = 0.5f * (h2 + other);
        out[blockIdx.x * S + seq] = 1.f / (1.f + __expf(-m));
    }
}

extern "C" void kernel_launch(void* const* d_in, const int* in_sizes, int n_in,
                              void* d_out, int out_size)
{
    const float* x   = (const float*)d_in[0];
    const float* w0f = (const float*)d_in[1];
    const float* u0f = (const float*)d_in[2];
    const float* b0f = (const float*)d_in[3];
    const float* w0b = (const float*)d_in[4];
    const float* u0b = (const float*)d_in[5];
    const float* b0b = (const float*)d_in[6];
    const float* w1f = (const float*)d_in[7];   // [3,1,40]
    const float* u1f = (const float*)d_in[8];   // [3,10,40]
    const float* b1f = (const float*)d_in[9];   // [3,40]
    const float* w1b = (const float*)d_in[10];
    const float* u1b = (const float*)d_in[11];
    const float* b1b = (const float*)d_in[12];
    const float* vF  = (const float*)d_in[13];  // [4,20,4]
    const float* rF  = (const float*)d_in[14];  // [4,1,4]
    const float* cF  = (const float*)d_in[15];  // [4,4]
    const float* vB  = (const float*)d_in[16];
    const float* rB  = (const float*)d_in[17];
    const float* cB  = (const float*)d_in[18];
    float* out = (float*)d_out;

    float *buf0, *buf1, *buf2;
    cudaGetSymbolAddress((void**)&buf0, g_buf0);
    cudaGetSymbolAddress((void**)&buf1, g_buf1);
    cudaGetSymbolAddress((void**)&buf2, g_buf2);

    const size_t smem5 = (size_t)smem_floats(5) * sizeof(float);
    const size_t smem1 = (size_t)smem_floats(1) * sizeof(float);
    cudaFuncSetAttribute(agg_kernel<5>, cudaFuncAttributeMaxDynamicSharedMemorySize, (int)smem5);
    cudaFuncSetAttribute(agg_kernel<1>, cudaFuncAttributeMaxDynamicSharedMemorySize, (int)smem1);

    // level 0: x[16,262144,5] -> buf0[524288]
    agg_kernel<5><<<524288 / S, BLOCK, smem5>>>(
        x, buf0,
        w0f, u0f, b0f, w0b, u0b, b0b,
        vF + 0, rF + 0, cF + 0, vB + 0, rB + 0, cB + 0);

    // level 1: buf0 -> buf1[65536]
    agg_kernel<1><<<65536 / S, BLOCK, smem1>>>(
        buf0, buf1,
        w1f + 0 * 40, u1f + 0 * 400, b1f + 0 * 40,
        w1b + 0 * 40, u1b + 0 * 400, b1b + 0 * 40,
        vF + 1 * 80, rF + 1 * 4, cF + 1 * 4,
        vB + 1 * 80, rB + 1 * 4, cB + 1 * 4);

    // level 2: buf1 -> buf2[8192]
    agg_kernel<1><<<8192 / S, BLOCK, smem1>>>(
        buf1, buf2,
        w1f + 1 * 40, u1f + 1 * 400, b1f + 1 * 40,
        w1b + 1 * 40, u1b + 1 * 400, b1b + 1 * 40,
        vF + 2 * 80, rF + 2 * 4, cF + 2 * 4,
        vB + 2 * 80, rB + 2 * 4, cB + 2 * 4);

    // level 3: buf2 -> out[1024]  ([16,64,1])
    agg_kernel<1><<<1024 / S, BLOCK, smem1>>>(
        buf2, out,
        w1f + 2 * 40, u1f + 2 * 400, b1f + 2 * 40,
        w1b + 2 * 40, u1b + 2 * 400, b1b + 2 * 40,
        vF + 3 * 80, rF + 3 * 4, cF + 3 * 4,
        vB + 3 * 80, rB + 3 * 4, cB + 3 * 4);
}